// round 16
// baseline (speedup 1.0000x reference)
#include <cuda_runtime.h>
#include <cuda_fp16.h>
#include <math.h>
#include <stdint.h>

#define NN    50000
#define EE    600000
#define DD    128
#define RREL2 474          /* 2R */
#define QQ    128
#define KTOT  1664         /* 13*D */
#define RELSZ (RREL2*DD)   /* 60672 */
#define NKT   52           /* K tiles of 32 */
#define NBLK  196          /* scan blocks of 256 */

// -------- scratch (static device globals; no allocation allowed) --------
__device__ __align__(16) float    g_rel[RELSZ];
__device__ int      g_row_start[NN + 1];
__device__ int      g_cursor[NN];
__device__ unsigned g_packed[EE];                 // src (16b) | attr<<16
__device__ __align__(16) __half   g_feat16[(size_t)NN * 4 * DD]; // F [N,512] fp16
__device__ __align__(16) __half   g_nf16[(size_t)NN * DD];       // nf fp16
__device__ float    g_logdeg[NN];
__device__ float    g_logdeg_mean;
__device__ int      g_bsum[256];
__device__ float    g_lsum[256];
__device__ int      g_boff[256];
// Wlin permuted to grouped-K, tile-major [kt][j(128)][k(32)], fp16:
__device__ __align__(16) __half   g_wH[NKT * 4096];

// ========================= helpers ==========================
__device__ __forceinline__ uint32_t smem_u32(const void* p) {
    uint32_t a;
    asm("{ .reg .u64 t; cvta.to.shared.u64 t, %1; cvt.u32.u64 %0, t; }"
        : "=r"(a) : "l"(p));
    return a;
}
__device__ __forceinline__ void cp16(uint32_t s, const void* g) {
    asm volatile("cp.async.cg.shared.global [%0], [%1], 16;" :: "r"(s), "l"(g));
}
#define CP_COMMIT() asm volatile("cp.async.commit_group;" ::: "memory")
#define CP_WAIT0()  asm volatile("cp.async.wait_group 0;" ::: "memory")

__device__ __forceinline__ void mma16816(float* d, const uint32_t* a,
                                         const uint32_t* b) {
    asm volatile(
        "mma.sync.aligned.m16n8k16.row.col.f32.f16.f16.f32 "
        "{%0,%1,%2,%3},{%4,%5,%6,%7},{%8,%9},{%0,%1,%2,%3};"
        : "+f"(d[0]), "+f"(d[1]), "+f"(d[2]), "+f"(d[3])
        : "r"(a[0]), "r"(a[1]), "r"(a[2]), "r"(a[3]), "r"(b[0]), "r"(b[1]));
}
__device__ __forceinline__ void ldsm4(uint32_t& r0, uint32_t& r1,
                                      uint32_t& r2, uint32_t& r3, uint32_t addr) {
    asm volatile("ldmatrix.sync.aligned.m8n8.x4.shared.b16 {%0,%1,%2,%3}, [%4];"
                 : "=r"(r0), "=r"(r1), "=r"(r2), "=r"(r3) : "r"(addr));
}

// ======================= K1: rel = query @ Wr^T + br =======================
__global__ void rel_kernel(const float* __restrict__ Wr,
                           const float* __restrict__ br,
                           const float* __restrict__ query) {
    int warp = (blockIdx.x * blockDim.x + threadIdx.x) >> 5;
    int lane = threadIdx.x & 31;
    if (warp >= RELSZ) return;
    const float* w = Wr + (size_t)warp * QQ;
    float s = w[lane]      * __ldg(&query[lane])
            + w[lane + 32] * __ldg(&query[lane + 32])
            + w[lane + 64] * __ldg(&query[lane + 64])
            + w[lane + 96] * __ldg(&query[lane + 96]);
    #pragma unroll
    for (int o = 16; o; o >>= 1) s += __shfl_xor_sync(0xffffffffu, s, o);
    if (lane == 0) g_rel[warp] = s + br[warp];
}

// =============== K1b: nf -> fp16 copy =====================================
__global__ void nf16_kernel(const float* __restrict__ nf) {
    int i = blockIdx.x * blockDim.x + threadIdx.x;   // over float4 groups
    if (i >= NN * DD / 4) return;
    float4 v = *(const float4*)&nf[i * 4];
    __half2 h0 = __floats2half2_rn(v.x, v.y);
    __half2 h1 = __floats2half2_rn(v.z, v.w);
    *(uint2*)&g_nf16[i * 4] = make_uint2(*(uint32_t*)&h0, *(uint32_t*)&h1);
}

// ==== K2a: per-block sums of int(degree) + logdeg partial sums ====
__global__ void scan1_kernel(const float* __restrict__ degout) {
    int b = blockIdx.x, t = threadIdx.x, i = b * 256 + t;
    int lane = t & 31, w = t >> 5;
    float dgf = (i < NN) ? degout[i] : 0.f;
    int   v   = (i < NN) ? (int)(dgf + 0.5f) : 0;
    float ld  = (i < NN) ? logf(dgf + 1.0f) : 0.f;
    if (i < NN) g_logdeg[i] = ld;
    __shared__ int   ish[8];
    __shared__ float fsh[8];
    int s = v; float f = ld;
    #pragma unroll
    for (int o = 16; o; o >>= 1) {
        s += __shfl_xor_sync(0xffffffffu, s, o);
        f += __shfl_xor_sync(0xffffffffu, f, o);
    }
    if (lane == 0) { ish[w] = s; fsh[w] = f; }
    __syncthreads();
    if (t == 0) {
        int S = 0; float F = 0.f;
        #pragma unroll
        for (int j = 0; j < 8; j++) { S += ish[j]; F += fsh[j]; }
        g_bsum[b] = S; g_lsum[b] = F;
    }
}

// ==== K2b: 1-block exclusive scan of block sums + logdeg mean ====
__global__ void scan2_kernel() {
    int t = threadIdx.x, lane = t & 31, w = t >> 5;
    __shared__ int   wsh[8];
    __shared__ float fsh[8];
    int   v = (t < NBLK) ? g_bsum[t] : 0;
    float f = (t < NBLK) ? g_lsum[t] : 0.f;
    int x = v;
    #pragma unroll
    for (int o = 1; o < 32; o <<= 1) {
        int y = __shfl_up_sync(0xffffffffu, x, o);
        if (lane >= o) x += y;
    }
    #pragma unroll
    for (int o = 16; o; o >>= 1) f += __shfl_xor_sync(0xffffffffu, f, o);
    if (lane == 31) wsh[w] = x;
    if (lane == 0)  fsh[w] = f;
    __syncthreads();
    if (t == 0) {
        int c = 0;
        #pragma unroll
        for (int j = 0; j < 8; j++) { int tmp = wsh[j]; wsh[j] = c; c += tmp; }
        g_row_start[NN] = c;
        float F = 0.f;
        #pragma unroll
        for (int j = 0; j < 8; j++) F += fsh[j];
        g_logdeg_mean = F / (float)NN;
    }
    __syncthreads();
    if (t < NBLK) g_boff[t] = x - v + wsh[w];
}

// ==== K2c: per-block rescan + global offset -> row_start, cursor ====
__global__ void scan3_kernel(const float* __restrict__ degout) {
    int b = blockIdx.x, t = threadIdx.x, i = b * 256 + t;
    int lane = t & 31, w = t >> 5;
    __shared__ int wsh[8];
    int v = (i < NN) ? (int)(degout[i] + 0.5f) : 0;
    int x = v;
    #pragma unroll
    for (int o = 1; o < 32; o <<= 1) {
        int y = __shfl_up_sync(0xffffffffu, x, o);
        if (lane >= o) x += y;
    }
    if (lane == 31) wsh[w] = x;
    __syncthreads();
    if (t == 0) {
        int c = 0;
        #pragma unroll
        for (int j = 0; j < 8; j++) { int tmp = wsh[j]; wsh[j] = c; c += tmp; }
    }
    __syncthreads();
    if (i < NN) {
        int excl = x - v + wsh[w] + g_boff[b];
        g_row_start[i] = excl;
        g_cursor[i]    = excl;
    }
}

// ================= K3: bucket edges into CSR slots ========================
__global__ void fill_kernel(const int* __restrict__ ei,
                            const int* __restrict__ ea) {
    int e = blockIdx.x * blockDim.x + threadIdx.x;
    if (e >= EE) return;
    int src = ei[e];
    int dst = ei[EE + e];
    int a   = ea[e];
    int pos = atomicAdd(&g_cursor[dst], 1);
    g_packed[pos] = (unsigned)src | ((unsigned)a << 16);
}

// ===== K4: permute Wlin to grouped-K tile-major [kt][j][k], fp16 =====
__global__ void wperm_kernel(const float* __restrict__ Wlin) {
    int kt = blockIdx.x;
    int t  = threadIdx.x;
    #pragma unroll
    for (int i = 0; i < 16; i++) {
        int e  = t + i * 256;          // 0..4095
        int j  = e >> 5;
        int kl = e & 31;
        int cp = kt * 32 + kl;
        int c;
        if (cp < 128) c = cp;
        else { int m = cp - 128; int s = m >> 9; int f = m & 511; c = 128 + 3 * f + s; }
        g_wH[(size_t)kt * 4096 + j * 32 + kl] = __float2half(Wlin[(size_t)j * KTOT + c]);
    }
}

// ====== K5: per-node gather reduction, 4-way edge unroll, fp16 stores ======
__global__ void agg_kernel(const float* __restrict__ nf,
                           const float* __restrict__ boundary,
                           const float* __restrict__ degout) {
    int n    = (blockIdx.x * blockDim.x + threadIdx.x) >> 5;
    int lane = threadIdx.x & 31;
    if (n >= NN) return;
    int beg = g_row_start[n], end = g_row_start[n + 1];
    int c0 = lane * 4;

    float sum[4] = {0.f, 0.f, 0.f, 0.f};
    float sq[4]  = {0.f, 0.f, 0.f, 0.f};
    float mx[4]  = {-INFINITY, -INFINITY, -INFINITY, -INFINITY};
    float mn[4]  = {INFINITY, INFINITY, INFINITY, INFINITY};

    int e = beg;
    for (; e + 3 < end; e += 4) {
        unsigned pk[4];
        #pragma unroll
        for (int u = 0; u < 4; u++) pk[u] = g_packed[e + u];
        float4 s4[4], f4[4];
        #pragma unroll
        for (int u = 0; u < 4; u++) {
            s4[u] = *(const float4*)(nf    + (size_t)(pk[u] & 0xFFFFu) * DD + c0);
            f4[u] = *(const float4*)(g_rel + (size_t)(pk[u] >> 16) * DD + c0);
        }
        #pragma unroll
        for (int u = 0; u < 4; u++) {
            float m0 = s4[u].x * f4[u].x, m1 = s4[u].y * f4[u].y;
            float m2 = s4[u].z * f4[u].z, m3 = s4[u].w * f4[u].w;
            sum[0] += m0; sum[1] += m1; sum[2] += m2; sum[3] += m3;
            sq[0] += m0 * m0; sq[1] += m1 * m1; sq[2] += m2 * m2; sq[3] += m3 * m3;
            mx[0] = fmaxf(mx[0], m0); mx[1] = fmaxf(mx[1], m1);
            mx[2] = fmaxf(mx[2], m2); mx[3] = fmaxf(mx[3], m3);
            mn[0] = fminf(mn[0], m0); mn[1] = fminf(mn[1], m1);
            mn[2] = fminf(mn[2], m2); mn[3] = fminf(mn[3], m3);
        }
    }
    for (; e < end; e++) {
        unsigned p = g_packed[e];
        float4 s4 = *(const float4*)(nf    + (size_t)(p & 0xFFFFu) * DD + c0);
        float4 f4 = *(const float4*)(g_rel + (size_t)(p >> 16) * DD + c0);
        float m0 = s4.x * f4.x, m1 = s4.y * f4.y, m2 = s4.z * f4.z, m3 = s4.w * f4.w;
        sum[0] += m0; sum[1] += m1; sum[2] += m2; sum[3] += m3;
        sq[0] += m0 * m0; sq[1] += m1 * m1; sq[2] += m2 * m2; sq[3] += m3 * m3;
        mx[0] = fmaxf(mx[0], m0); mx[1] = fmaxf(mx[1], m1);
        mx[2] = fmaxf(mx[2], m2); mx[3] = fmaxf(mx[3], m3);
        mn[0] = fminf(mn[0], m0); mn[1] = fminf(mn[1], m1);
        mn[2] = fminf(mn[2], m2); mn[3] = fminf(mn[3], m3);
    }

    float d0  = degout[n];
    float deg = d0 + 1.0f;
    bool  has_edge = (d0 > 0.0f);
    float inv = 1.0f / deg;
    float4 b = *(const float4*)(boundary + (size_t)n * DD + c0);
    float bs[4] = {b.x, b.y, b.z, b.w};

    #pragma unroll
    for (int u = 0; u < 4; u++) {
        float bb = bs[u];
        float mean   = (sum[u] + bb) * inv;
        float sqmean = (sq[u] + bb * bb) * inv;
        float vmx = has_edge ? mx[u] : 0.0f;
        float vmn = has_edge ? mn[u] : 0.0f;
        vmx = fmaxf(vmx, bb);
        vmn = fminf(vmn, bb);
        float sd = sqrtf(fmaxf(sqmean - mean * mean, 1e-6f));
        __half2 h0 = __floats2half2_rn(mean, vmx);
        __half2 h1 = __floats2half2_rn(vmn, sd);
        *(uint2*)&g_feat16[(size_t)n * 512 + (c0 + u) * 4] =
            make_uint2(*(uint32_t*)&h0, *(uint32_t*)&h1);
    }
}

// ====== K6: fp16 HMMA GEMM, ldmatrix fragment loads, fused epilogue =========
// 128x128 tile, BK=32, 256 threads, 8 warps in 4(row)x2(col).
// Fragments via ldmatrix.m8n8.x4: 4 LDSM for A + 8 LDSM for B per warp per kt
// (was 48 LDS.32). HSTR=40 rows partition all 32 banks -> conflict-free LDSM.
#define HSTR 40                       /* fp16 stride per row */
#define AH_F (128 * HSTR)             /* fp16 per A buffer (5120) */

__global__ void __launch_bounds__(256)
gemm_hmma(const float* __restrict__ blin,
          float* __restrict__ out) {
    __shared__ __half As[2][AH_F];
    __shared__ __half Bs[2][AH_F];
    __shared__ float  sc1[128];
    __shared__ float  sc2[128];

    const int t    = threadIdx.x;
    const int n0   = blockIdx.x * 128;
    const int w    = t >> 5;
    const int lane = t & 31;
    const int wr   = w >> 1;          // warp row: rows 32*wr..32*wr+31
    const int wc   = w & 1;           // warp col: cols 64*wc..
    const int qr   = lane >> 2;       // fragment quad-row 0..7
    const int qc   = (lane & 3) * 2;  // fragment k / col offset
    const int rl   = t >> 1;          // A-build row (0..127)
    const int ph   = t & 1;           // fp16-col half: cols [ph*16, ph*16+16)
    const int t8   = lane >> 3;       // ldmatrix tile id 0..3
    const int r8   = lane & 7;        // ldmatrix row within tile

    if (t < 128) {
        int n = n0 + t;
        float scale = 0.f;
        if (n < NN) scale = g_logdeg[n] / (g_logdeg_mean + 1e-10f);
        sc1[t] = scale;
        sc2[t] = 1.0f / fmaxf(scale, 0.01f);
    }
    __syncthreads();

    const uint32_t asAddr0 = smem_u32(&As[0][0]);
    const uint32_t asAddr1 = smem_u32(&As[1][0]);
    const uint32_t bsAddr0 = smem_u32(&Bs[0][0]);
    const uint32_t bsAddr1 = smem_u32(&Bs[1][0]);

    // ---- precompute per-thread ldmatrix relative offsets (bytes) ----
    // A frag (rb, kc): tiles {rows, rows+8, k+8, rows+8&k+8}
    uint32_t aRel[2][2];
    #pragma unroll
    for (int rb = 0; rb < 2; rb++)
        #pragma unroll
        for (int kc = 0; kc < 2; kc++) {
            int row = wr * 32 + rb * 16 + (t8 & 1) * 8 + r8;
            int col = kc * 16 + (t8 >> 1) * 8;
            aRel[rb][kc] = (uint32_t)(row * HSTR + col) * 2;
        }
    // B frag pair (kc, nbp): tiles {j-lo/k-lo, j-lo/k-hi, j-hi/k-lo, j-hi/k-hi}
    uint32_t bRel[2][4];
    #pragma unroll
    for (int kc = 0; kc < 2; kc++)
        #pragma unroll
        for (int nbp = 0; nbp < 4; nbp++) {
            int j = wc * 64 + nbp * 16 + (t8 >> 1) * 8 + r8;
            int k = kc * 16 + (t8 & 1) * 8;
            bRel[kc][nbp] = (uint32_t)(j * HSTR + k) * 2;
        }

    // scaled-group staging regs (16 fp16 = 4 uint2 per thread)
    uint2 avh[4];
    auto ldA = [&](int kt) {
        if (kt >= 20) {
            int n = n0 + rl;
            int f0 = kt * 32 - ((kt >= 36) ? 1152 : 640) + ph * 16;
            if (n < NN) {
                const __half* src = &g_feat16[(size_t)n * 512 + f0];
                avh[0] = *(const uint2*)(src);
                avh[1] = *(const uint2*)(src + 4);
                avh[2] = *(const uint2*)(src + 8);
                avh[3] = *(const uint2*)(src + 12);
            } else {
                avh[0] = avh[1] = avh[2] = avh[3] = make_uint2(0, 0);
            }
        }
    };
    auto stA = [&](int kt, int buf) {
        uint32_t base = buf ? asAddr1 : asAddr0;
        uint32_t dst = base + (rl * HSTR + ph * 16) * 2;   // bytes
        if (kt < 20) {
            bool ok = (n0 + rl) < NN;
            const char* src;
            if (kt < 4)
                src = (const char*)&g_nf16[(size_t)(n0 + rl) * DD + kt * 32 + ph * 16];
            else
                src = (const char*)&g_feat16[(size_t)(n0 + rl) * 512 + (kt - 4) * 32 + ph * 16];
            if (ok) {
                cp16(dst, src);
                cp16(dst + 16, src + 16);
            } else {
                *(uint4*)(&As[buf][rl * HSTR + ph * 16])     = make_uint4(0, 0, 0, 0);
                *(uint4*)(&As[buf][rl * HSTR + ph * 16 + 8]) = make_uint4(0, 0, 0, 0);
            }
            CP_COMMIT();
        } else {
            float s = (kt >= 36) ? sc2[rl] : sc1[rl];
            __half2 hs = __float2half2_rn(s);
            uint2 o[4];
            #pragma unroll
            for (int u = 0; u < 4; u++) {
                __half2* iv = (__half2*)&avh[u];
                __half2* ov = (__half2*)&o[u];
                ov[0] = __hmul2(iv[0], hs);
                ov[1] = __hmul2(iv[1], hs);
            }
            *(uint4*)(&As[buf][rl * HSTR + ph * 16])     = make_uint4(o[0].x, o[0].y, o[1].x, o[1].y);
            *(uint4*)(&As[buf][rl * HSTR + ph * 16 + 8]) = make_uint4(o[2].x, o[2].y, o[3].x, o[3].y);
            CP_COMMIT();   // keep group count consistent
        }
    };
    auto ldB = [&](int kt, int buf) {
        const char* src = (const char*)&g_wH[(size_t)kt * 4096];
        uint32_t base = buf ? bsAddr1 : bsAddr0;
        #pragma unroll
        for (int i = 0; i < 2; i++) {
            int ch = t + i * 256;          // 0..511
            int j = ch >> 2, part = ch & 3;
            cp16(base + j * (HSTR * 2) + part * 16, src + j * 64 + part * 16);
        }
        CP_COMMIT();
    };

    float acc[2][8][4];
    #pragma unroll
    for (int rb = 0; rb < 2; rb++)
        #pragma unroll
        for (int nb = 0; nb < 8; nb++)
            #pragma unroll
            for (int q = 0; q < 4; q++) acc[rb][nb][q] = 0.f;

    ldA(0);
    ldB(0, 0);
    stA(0, 0);
    CP_WAIT0();
    __syncthreads();

    int cur = 0;
    for (int kt = 0; kt < NKT; kt++) {
        if (kt + 1 < NKT) {
            ldA(kt + 1);
            ldB(kt + 1, cur ^ 1);
        }
        uint32_t ab = cur ? asAddr1 : asAddr0;
        uint32_t bb = cur ? bsAddr1 : bsAddr0;
        #pragma unroll
        for (int kc = 0; kc < 2; kc++) {
            uint32_t afr[2][4];
            #pragma unroll
            for (int rb = 0; rb < 2; rb++)
                ldsm4(afr[rb][0], afr[rb][1], afr[rb][2], afr[rb][3],
                      ab + aRel[rb][kc]);
            #pragma unroll
            for (int nbp = 0; nbp < 4; nbp++) {
                uint32_t b0, b1, b2, b3;
                ldsm4(b0, b1, b2, b3, bb + bRel[kc][nbp]);
                uint32_t blo[2] = {b0, b1};
                uint32_t bhi[2] = {b2, b3};
                mma16816(acc[0][2 * nbp],     afr[0], blo);
                mma16816(acc[1][2 * nbp],     afr[1], blo);
                mma16816(acc[0][2 * nbp + 1], afr[0], bhi);
                mma16816(acc[1][2 * nbp + 1], afr[1], bhi);
            }
        }
        if (kt + 1 < NKT) {
            stA(kt + 1, cur ^ 1);
            CP_WAIT0();
        }
        __syncthreads();
        cur ^= 1;
    }

    // ---- epilogue: bias + relu (d0,d1 -> row r; d2,d3 -> row r+8) ----
    #pragma unroll
    for (int nb = 0; nb < 8; nb++) {
        int j = wc * 64 + nb * 8 + qc;
        float2 bl = __ldg((const float2*)&blin[j]);
        #pragma unroll
        for (int rb = 0; rb < 2; rb++) {
            int n = n0 + wr * 32 + rb * 16 + qr;
            if (n < NN) {
                float2 o;
                o.x = fmaxf(acc[rb][nb][0] + bl.x, 0.f);
                o.y = fmaxf(acc[rb][nb][1] + bl.y, 0.f);
                *(float2*)&out[(size_t)n * DD + j] = o;
            }
            if (n + 8 < NN) {
                float2 o;
                o.x = fmaxf(acc[rb][nb][2] + bl.x, 0.f);
                o.y = fmaxf(acc[rb][nb][3] + bl.y, 0.f);
                *(float2*)&out[(size_t)(n + 8) * DD + j] = o;
            }
        }
    }
}

// ============================== launch ====================================
extern "C" void kernel_launch(void* const* d_in, const int* in_sizes, int n_in,
                              void* d_out, int out_size) {
    const float* nf    = (const float*)d_in[0];   // node_features [N,D]
    const float* query = (const float*)d_in[1];   // [1,Q]
    const float* bnd   = (const float*)d_in[2];   // boundary [N,D]
    const float* deg   = (const float*)d_in[3];   // degree_out [N]
    const float* Wr    = (const float*)d_in[4];   // [2R*D, Q]
    const float* br    = (const float*)d_in[5];   // [2R*D]
    const float* Wlin  = (const float*)d_in[6];   // [D, 13D]
    const float* blin  = (const float*)d_in[7];   // [D]
    const int*   ei    = (const int*)d_in[8];     // edge_index [2,E] int32
    const int*   ea    = (const int*)d_in[9];     // edge_attr [E] int32
    float*       out   = (float*)d_out;           // [N,D]

    rel_kernel  <<<(RELSZ * 32 + 255) / 256, 256>>>(Wr, br, query);
    nf16_kernel <<<(NN * DD / 4 + 255) / 256, 256>>>(nf);
    scan1_kernel<<<NBLK, 256>>>(deg);
    scan2_kernel<<<1, 256>>>();
    scan3_kernel<<<NBLK, 256>>>(deg);
    fill_kernel <<<(EE + 255) / 256, 256>>>(ei, ea);
    wperm_kernel<<<NKT, 256>>>(Wlin);
    agg_kernel  <<<(NN * 32 + 255) / 256, 256>>>(nf, bnd, deg);
    gemm_hmma   <<<(NN + 127) / 128, 256>>>(blin, out);
}

// round 17
// speedup vs baseline: 1.1208x; 1.1208x over previous
#include <cuda_runtime.h>
#include <cuda_fp16.h>
#include <math.h>
#include <stdint.h>

#define NN    50000
#define EE    600000
#define DD    128
#define RREL2 474          /* 2R */
#define QQ    128
#define KTOT  1664         /* 13*D */
#define RELSZ (RREL2*DD)   /* 60672 */
#define NKT   52           /* K tiles of 32 */
#define NBLK  196          /* scan blocks of 256 */

// -------- scratch (static device globals; no allocation allowed) --------
__device__ __align__(16) __half   g_rel16[RELSZ];
__device__ int      g_row_start[NN + 1];
__device__ int      g_cursor[NN];
__device__ unsigned g_packed[EE];                 // src (16b) | attr<<16
__device__ __align__(16) __half   g_feat16[(size_t)NN * 4 * DD]; // F [N,512] fp16
__device__ __align__(16) __half   g_nf16[(size_t)NN * DD];       // nf fp16
__device__ float    g_logdeg[NN];
__device__ float    g_logdeg_mean;
__device__ int      g_bsum[256];
__device__ float    g_lsum[256];
__device__ int      g_boff[256];
// Wlin permuted to grouped-K, tile-major [kt][j(128)][k(32)], fp16:
__device__ __align__(16) __half   g_wH[NKT * 4096];

// ========================= helpers ==========================
__device__ __forceinline__ uint32_t smem_u32(const void* p) {
    uint32_t a;
    asm("{ .reg .u64 t; cvta.to.shared.u64 t, %1; cvt.u32.u64 %0, t; }"
        : "=r"(a) : "l"(p));
    return a;
}
__device__ __forceinline__ void cp16(uint32_t s, const void* g) {
    asm volatile("cp.async.cg.shared.global [%0], [%1], 16;" :: "r"(s), "l"(g));
}
#define CP_COMMIT() asm volatile("cp.async.commit_group;" ::: "memory")
#define CP_WAIT0()  asm volatile("cp.async.wait_group 0;" ::: "memory")

__device__ __forceinline__ void mma16816(float* d, const uint32_t* a,
                                         const uint32_t* b) {
    asm volatile(
        "mma.sync.aligned.m16n8k16.row.col.f32.f16.f16.f32 "
        "{%0,%1,%2,%3},{%4,%5,%6,%7},{%8,%9},{%0,%1,%2,%3};"
        : "+f"(d[0]), "+f"(d[1]), "+f"(d[2]), "+f"(d[3])
        : "r"(a[0]), "r"(a[1]), "r"(a[2]), "r"(a[3]), "r"(b[0]), "r"(b[1]));
}

// ======================= K1: rel = query @ Wr^T + br (fp16 out) ============
__global__ void rel_kernel(const float* __restrict__ Wr,
                           const float* __restrict__ br,
                           const float* __restrict__ query) {
    int warp = (blockIdx.x * blockDim.x + threadIdx.x) >> 5;
    int lane = threadIdx.x & 31;
    if (warp >= RELSZ) return;
    const float* w = Wr + (size_t)warp * QQ;
    float s = w[lane]      * __ldg(&query[lane])
            + w[lane + 32] * __ldg(&query[lane + 32])
            + w[lane + 64] * __ldg(&query[lane + 64])
            + w[lane + 96] * __ldg(&query[lane + 96]);
    #pragma unroll
    for (int o = 16; o; o >>= 1) s += __shfl_xor_sync(0xffffffffu, s, o);
    if (lane == 0) g_rel16[warp] = __float2half(s + br[warp]);
}

// =============== K1b: nf -> fp16 copy =====================================
__global__ void nf16_kernel(const float* __restrict__ nf) {
    int i = blockIdx.x * blockDim.x + threadIdx.x;   // over float4 groups
    if (i >= NN * DD / 4) return;
    float4 v = *(const float4*)&nf[i * 4];
    __half2 h0 = __floats2half2_rn(v.x, v.y);
    __half2 h1 = __floats2half2_rn(v.z, v.w);
    *(uint2*)&g_nf16[i * 4] = make_uint2(*(uint32_t*)&h0, *(uint32_t*)&h1);
}

// ==== K2a: per-block sums of int(degree) + logdeg partial sums ====
__global__ void scan1_kernel(const float* __restrict__ degout) {
    int b = blockIdx.x, t = threadIdx.x, i = b * 256 + t;
    int lane = t & 31, w = t >> 5;
    float dgf = (i < NN) ? degout[i] : 0.f;
    int   v   = (i < NN) ? (int)(dgf + 0.5f) : 0;
    float ld  = (i < NN) ? logf(dgf + 1.0f) : 0.f;
    if (i < NN) g_logdeg[i] = ld;
    __shared__ int   ish[8];
    __shared__ float fsh[8];
    int s = v; float f = ld;
    #pragma unroll
    for (int o = 16; o; o >>= 1) {
        s += __shfl_xor_sync(0xffffffffu, s, o);
        f += __shfl_xor_sync(0xffffffffu, f, o);
    }
    if (lane == 0) { ish[w] = s; fsh[w] = f; }
    __syncthreads();
    if (t == 0) {
        int S = 0; float F = 0.f;
        #pragma unroll
        for (int j = 0; j < 8; j++) { S += ish[j]; F += fsh[j]; }
        g_bsum[b] = S; g_lsum[b] = F;
    }
}

// ==== K2b: 1-block exclusive scan of block sums + logdeg mean ====
__global__ void scan2_kernel() {
    int t = threadIdx.x, lane = t & 31, w = t >> 5;
    __shared__ int   wsh[8];
    __shared__ float fsh[8];
    int   v = (t < NBLK) ? g_bsum[t] : 0;
    float f = (t < NBLK) ? g_lsum[t] : 0.f;
    int x = v;
    #pragma unroll
    for (int o = 1; o < 32; o <<= 1) {
        int y = __shfl_up_sync(0xffffffffu, x, o);
        if (lane >= o) x += y;
    }
    #pragma unroll
    for (int o = 16; o; o >>= 1) f += __shfl_xor_sync(0xffffffffu, f, o);
    if (lane == 31) wsh[w] = x;
    if (lane == 0)  fsh[w] = f;
    __syncthreads();
    if (t == 0) {
        int c = 0;
        #pragma unroll
        for (int j = 0; j < 8; j++) { int tmp = wsh[j]; wsh[j] = c; c += tmp; }
        g_row_start[NN] = c;
        float F = 0.f;
        #pragma unroll
        for (int j = 0; j < 8; j++) F += fsh[j];
        g_logdeg_mean = F / (float)NN;
    }
    __syncthreads();
    if (t < NBLK) g_boff[t] = x - v + wsh[w];
}

// ==== K2c: per-block rescan + global offset -> row_start, cursor ====
__global__ void scan3_kernel(const float* __restrict__ degout) {
    int b = blockIdx.x, t = threadIdx.x, i = b * 256 + t;
    int lane = t & 31, w = t >> 5;
    __shared__ int wsh[8];
    int v = (i < NN) ? (int)(degout[i] + 0.5f) : 0;
    int x = v;
    #pragma unroll
    for (int o = 1; o < 32; o <<= 1) {
        int y = __shfl_up_sync(0xffffffffu, x, o);
        if (lane >= o) x += y;
    }
    if (lane == 31) wsh[w] = x;
    __syncthreads();
    if (t == 0) {
        int c = 0;
        #pragma unroll
        for (int j = 0; j < 8; j++) { int tmp = wsh[j]; wsh[j] = c; c += tmp; }
    }
    __syncthreads();
    if (i < NN) {
        int excl = x - v + wsh[w] + g_boff[b];
        g_row_start[i] = excl;
        g_cursor[i]    = excl;
    }
}

// ================= K3: bucket edges into CSR slots ========================
__global__ void fill_kernel(const int* __restrict__ ei,
                            const int* __restrict__ ea) {
    int e = blockIdx.x * blockDim.x + threadIdx.x;
    if (e >= EE) return;
    int src = ei[e];
    int dst = ei[EE + e];
    int a   = ea[e];
    int pos = atomicAdd(&g_cursor[dst], 1);
    g_packed[pos] = (unsigned)src | ((unsigned)a << 16);
}

// ===== K4: permute Wlin to grouped-K tile-major [kt][j][k], fp16 =====
__global__ void wperm_kernel(const float* __restrict__ Wlin) {
    int kt = blockIdx.x;
    int t  = threadIdx.x;
    #pragma unroll
    for (int i = 0; i < 16; i++) {
        int e  = t + i * 256;          // 0..4095
        int j  = e >> 5;
        int kl = e & 31;
        int cp = kt * 32 + kl;
        int c;
        if (cp < 128) c = cp;
        else { int m = cp - 128; int s = m >> 9; int f = m & 511; c = 128 + 3 * f + s; }
        g_wH[(size_t)kt * 4096 + j * 32 + kl] = __float2half(Wlin[(size_t)j * KTOT + c]);
    }
}

// ====== K5: per-node gather reduction, fp16 reads, 4-way edge unroll =======
__global__ void agg_kernel(const float* __restrict__ boundary,
                           const float* __restrict__ degout) {
    int n    = (blockIdx.x * blockDim.x + threadIdx.x) >> 5;
    int lane = threadIdx.x & 31;
    if (n >= NN) return;
    int beg = g_row_start[n], end = g_row_start[n + 1];
    int c0 = lane * 4;

    float sum[4] = {0.f, 0.f, 0.f, 0.f};
    float sq[4]  = {0.f, 0.f, 0.f, 0.f};
    float mx[4]  = {-INFINITY, -INFINITY, -INFINITY, -INFINITY};
    float mn[4]  = {INFINITY, INFINITY, INFINITY, INFINITY};

    auto accum = [&](uint2 sr, uint2 fr) {
        float2 s0 = __half22float2(*(__half2*)&sr.x);
        float2 s1 = __half22float2(*(__half2*)&sr.y);
        float2 f0 = __half22float2(*(__half2*)&fr.x);
        float2 f1 = __half22float2(*(__half2*)&fr.y);
        float m0 = s0.x * f0.x, m1 = s0.y * f0.y, m2 = s1.x * f1.x, m3 = s1.y * f1.y;
        sum[0] += m0; sum[1] += m1; sum[2] += m2; sum[3] += m3;
        sq[0] += m0 * m0; sq[1] += m1 * m1; sq[2] += m2 * m2; sq[3] += m3 * m3;
        mx[0] = fmaxf(mx[0], m0); mx[1] = fmaxf(mx[1], m1);
        mx[2] = fmaxf(mx[2], m2); mx[3] = fmaxf(mx[3], m3);
        mn[0] = fminf(mn[0], m0); mn[1] = fminf(mn[1], m1);
        mn[2] = fminf(mn[2], m2); mn[3] = fminf(mn[3], m3);
    };

    int e = beg;
    for (; e + 3 < end; e += 4) {
        unsigned pk[4];
        #pragma unroll
        for (int u = 0; u < 4; u++) pk[u] = g_packed[e + u];
        uint2 sr[4], fr[4];
        #pragma unroll
        for (int u = 0; u < 4; u++) {
            sr[u] = *(const uint2*)(g_nf16  + (size_t)(pk[u] & 0xFFFFu) * DD + c0);
            fr[u] = *(const uint2*)(g_rel16 + (size_t)(pk[u] >> 16) * DD + c0);
        }
        #pragma unroll
        for (int u = 0; u < 4; u++) accum(sr[u], fr[u]);
    }
    for (; e < end; e++) {
        unsigned p = g_packed[e];
        uint2 sr = *(const uint2*)(g_nf16  + (size_t)(p & 0xFFFFu) * DD + c0);
        uint2 fr = *(const uint2*)(g_rel16 + (size_t)(p >> 16) * DD + c0);
        accum(sr, fr);
    }

    float d0  = degout[n];
    float deg = d0 + 1.0f;
    bool  has_edge = (d0 > 0.0f);
    float inv = 1.0f / deg;
    float4 b = *(const float4*)(boundary + (size_t)n * DD + c0);
    float bs[4] = {b.x, b.y, b.z, b.w};

    #pragma unroll
    for (int u = 0; u < 4; u++) {
        float bb = bs[u];
        float mean   = (sum[u] + bb) * inv;
        float sqmean = (sq[u] + bb * bb) * inv;
        float vmx = has_edge ? mx[u] : 0.0f;
        float vmn = has_edge ? mn[u] : 0.0f;
        vmx = fmaxf(vmx, bb);
        vmn = fminf(vmn, bb);
        float sd = sqrtf(fmaxf(sqmean - mean * mean, 1e-6f));
        __half2 h0 = __floats2half2_rn(mean, vmx);
        __half2 h1 = __floats2half2_rn(vmn, sd);
        *(uint2*)&g_feat16[(size_t)n * 512 + (c0 + u) * 4] =
            make_uint2(*(uint32_t*)&h0, *(uint32_t*)&h1);
    }
}

// ============ K6: fp16 HMMA GEMM, fp16 X-build (R15-proven version) =========
// 128x128 tile, BK=32, 256 threads, 8 warps in 4(row)x2(col).
// A-build: thread owns row rl=t>>1, fp16 cols [ph*16, ph*16+16) (32B).
// Groups 0/1: two cp.async 16B copies. Groups 2/3: 16-fp16 load + HMUL2 + STS.
#define HSTR 40                       /* fp16 stride per row */
#define AH_F (128 * HSTR)             /* fp16 per A buffer (5120) */

__global__ void __launch_bounds__(256)
gemm_hmma(const float* __restrict__ blin,
          float* __restrict__ out) {
    __shared__ __half As[2][AH_F];
    __shared__ __half Bs[2][AH_F];
    __shared__ float  sc1[128];
    __shared__ float  sc2[128];

    const int t    = threadIdx.x;
    const int n0   = blockIdx.x * 128;
    const int w    = t >> 5;
    const int lane = t & 31;
    const int wr   = w >> 1;          // warp row: rows 32*wr..32*wr+31
    const int wc   = w & 1;           // warp col: cols 64*wc..
    const int qr   = lane >> 2;       // fragment quad-row 0..7
    const int qc   = (lane & 3) * 2;  // fragment k / col offset
    const int rl   = t >> 1;          // A-build row (0..127)
    const int ph   = t & 1;           // fp16-col half: cols [ph*16, ph*16+16)

    if (t < 128) {
        int n = n0 + t;
        float scale = 0.f;
        if (n < NN) scale = g_logdeg[n] / (g_logdeg_mean + 1e-10f);
        sc1[t] = scale;
        sc2[t] = 1.0f / fmaxf(scale, 0.01f);
    }
    __syncthreads();

    const uint32_t asAddr0 = smem_u32(&As[0][0]);
    const uint32_t asAddr1 = smem_u32(&As[1][0]);
    const uint32_t bsAddr0 = smem_u32(&Bs[0][0]);
    const uint32_t bsAddr1 = smem_u32(&Bs[1][0]);

    // scaled-group staging regs (16 fp16 = 4 uint2 per thread)
    uint2 avh[4];
    auto ldA = [&](int kt) {
        if (kt >= 20) {
            int n = n0 + rl;
            int f0 = kt * 32 - ((kt >= 36) ? 1152 : 640) + ph * 16;
            if (n < NN) {
                const __half* src = &g_feat16[(size_t)n * 512 + f0];
                avh[0] = *(const uint2*)(src);
                avh[1] = *(const uint2*)(src + 4);
                avh[2] = *(const uint2*)(src + 8);
                avh[3] = *(const uint2*)(src + 12);
            } else {
                avh[0] = avh[1] = avh[2] = avh[3] = make_uint2(0, 0);
            }
        }
    };
    auto stA = [&](int kt, int buf) {
        uint32_t base = buf ? asAddr1 : asAddr0;
        uint32_t dst = base + (rl * HSTR + ph * 16) * 2;   // bytes
        if (kt < 20) {
            bool ok = (n0 + rl) < NN;
            const char* src;
            if (kt < 4)
                src = (const char*)&g_nf16[(size_t)(n0 + rl) * DD + kt * 32 + ph * 16];
            else
                src = (const char*)&g_feat16[(size_t)(n0 + rl) * 512 + (kt - 4) * 32 + ph * 16];
            if (ok) {
                cp16(dst, src);
                cp16(dst + 16, src + 16);
            } else {
                *(uint4*)(&As[buf][rl * HSTR + ph * 16])     = make_uint4(0, 0, 0, 0);
                *(uint4*)(&As[buf][rl * HSTR + ph * 16 + 8]) = make_uint4(0, 0, 0, 0);
            }
            CP_COMMIT();
        } else {
            float s = (kt >= 36) ? sc2[rl] : sc1[rl];
            __half2 hs = __float2half2_rn(s);
            uint2 o[4];
            #pragma unroll
            for (int u = 0; u < 4; u++) {
                __half2* iv = (__half2*)&avh[u];
                __half2* ov = (__half2*)&o[u];
                ov[0] = __hmul2(iv[0], hs);
                ov[1] = __hmul2(iv[1], hs);
            }
            *(uint4*)(&As[buf][rl * HSTR + ph * 16])     = make_uint4(o[0].x, o[0].y, o[1].x, o[1].y);
            *(uint4*)(&As[buf][rl * HSTR + ph * 16 + 8]) = make_uint4(o[2].x, o[2].y, o[3].x, o[3].y);
            CP_COMMIT();   // keep group count consistent
        }
    };
    auto ldB = [&](int kt, int buf) {
        const char* src = (const char*)&g_wH[(size_t)kt * 4096];
        uint32_t base = buf ? bsAddr1 : bsAddr0;
        #pragma unroll
        for (int i = 0; i < 2; i++) {
            int ch = t + i * 256;          // 0..511
            int j = ch >> 2, part = ch & 3;
            cp16(base + j * (HSTR * 2) + part * 16, src + j * 64 + part * 16);
        }
        CP_COMMIT();
    };

    float acc[2][8][4];
    #pragma unroll
    for (int rb = 0; rb < 2; rb++)
        #pragma unroll
        for (int nb = 0; nb < 8; nb++)
            #pragma unroll
            for (int q = 0; q < 4; q++) acc[rb][nb][q] = 0.f;

    ldA(0);
    ldB(0, 0);
    stA(0, 0);
    CP_WAIT0();
    __syncthreads();

    int cur = 0;
    for (int kt = 0; kt < NKT; kt++) {
        if (kt + 1 < NKT) {
            ldA(kt + 1);
            ldB(kt + 1, cur ^ 1);
        }
        const __half* Ac = As[cur];
        const __half* Bc = Bs[cur];
        #pragma unroll
        for (int kc = 0; kc < 2; kc++) {
            int kb = kc * 16 + qc;
            uint32_t afr[2][4];
            #pragma unroll
            for (int rb = 0; rb < 2; rb++) {
                int r = wr * 32 + rb * 16 + qr;
                afr[rb][0] = *(const uint32_t*)&Ac[r * HSTR + kb];
                afr[rb][1] = *(const uint32_t*)&Ac[(r + 8) * HSTR + kb];
                afr[rb][2] = *(const uint32_t*)&Ac[r * HSTR + kb + 8];
                afr[rb][3] = *(const uint32_t*)&Ac[(r + 8) * HSTR + kb + 8];
            }
            #pragma unroll
            for (int nb = 0; nb < 8; nb++) {
                int j = wc * 64 + nb * 8 + qr;
                uint32_t bfr[2];
                bfr[0] = *(const uint32_t*)&Bc[j * HSTR + kc * 16 + qc];
                bfr[1] = *(const uint32_t*)&Bc[j * HSTR + kc * 16 + qc + 8];
                mma16816(acc[0][nb], afr[0], bfr);
                mma16816(acc[1][nb], afr[1], bfr);
            }
        }
        if (kt + 1 < NKT) {
            stA(kt + 1, cur ^ 1);
            CP_WAIT0();
        }
        __syncthreads();
        cur ^= 1;
    }

    // ---- epilogue: bias + relu (d0,d1 -> row r; d2,d3 -> row r+8) ----
    #pragma unroll
    for (int nb = 0; nb < 8; nb++) {
        int j = wc * 64 + nb * 8 + qc;
        float2 bl = __ldg((const float2*)&blin[j]);
        #pragma unroll
        for (int rb = 0; rb < 2; rb++) {
            int n = n0 + wr * 32 + rb * 16 + qr;
            if (n < NN) {
                float2 o;
                o.x = fmaxf(acc[rb][nb][0] + bl.x, 0.f);
                o.y = fmaxf(acc[rb][nb][1] + bl.y, 0.f);
                *(float2*)&out[(size_t)n * DD + j] = o;
            }
            if (n + 8 < NN) {
                float2 o;
                o.x = fmaxf(acc[rb][nb][2] + bl.x, 0.f);
                o.y = fmaxf(acc[rb][nb][3] + bl.y, 0.f);
                *(float2*)&out[(size_t)(n + 8) * DD + j] = o;
            }
        }
    }
}

// ============================== launch ====================================
extern "C" void kernel_launch(void* const* d_in, const int* in_sizes, int n_in,
                              void* d_out, int out_size) {
    const float* nf    = (const float*)d_in[0];   // node_features [N,D]
    const float* query = (const float*)d_in[1];   // [1,Q]
    const float* bnd   = (const float*)d_in[2];   // boundary [N,D]
    const float* deg   = (const float*)d_in[3];   // degree_out [N]
    const float* Wr    = (const float*)d_in[4];   // [2R*D, Q]
    const float* br    = (const float*)d_in[5];   // [2R*D]
    const float* Wlin  = (const float*)d_in[6];   // [D, 13D]
    const float* blin  = (const float*)d_in[7];   // [D]
    const int*   ei    = (const int*)d_in[8];     // edge_index [2,E] int32
    const int*   ea    = (const int*)d_in[9];     // edge_attr [E] int32
    float*       out   = (float*)d_out;           // [N,D]

    rel_kernel  <<<(RELSZ * 32 + 255) / 256, 256>>>(Wr, br, query);
    nf16_kernel <<<(NN * DD / 4 + 255) / 256, 256>>>(nf);
    scan1_kernel<<<NBLK, 256>>>(deg);
    scan2_kernel<<<1, 256>>>();
    scan3_kernel<<<NBLK, 256>>>(deg);
    fill_kernel <<<(EE + 255) / 256, 256>>>(ei, ea);
    wperm_kernel<<<NKT, 256>>>(Wlin);
    agg_kernel  <<<(NN * 32 + 255) / 256, 256>>>(bnd, deg);
    gemm_hmma   <<<(NN + 127) / 128, 256>>>(blin, out);
}